// round 15
// baseline (speedup 1.0000x reference)
#include <cuda_runtime.h>
#include <cuda_fp16.h>
#include <cstdint>
#include <math.h>
typedef long long ll;
typedef __half hf;
typedef __half2 hf2;

#define B_ 8
#define T_ 1024
#define DL 1024
#define NH 8
#define DKH 128
#define DFF 2048
#define FH 256
#define MROWS 8192

// ---------------- device scratch ----------------
__device__ __align__(128) hf    g_x2 [(size_t)MROWS*DL];
__device__ __align__(128) hf    g_W12[(size_t)DFF*DL];
__device__ __align__(128) hf    g_H12[(size_t)MROWS*DFF];
__device__ __align__(128) hf    g_W22[(size_t)DL*DFF];
__device__ __align__(128) hf    g_X  [(size_t)MROWS*DL];   // fp16 trunk
__device__ __align__(128) hf    g_Hn2[(size_t)MROWS*DL];
__device__ __align__(128) hf    g_Wq2[(size_t)2*DL*DL];
__device__ __align__(128) hf    g_Wk2[(size_t)2*DL*DL];
__device__ __align__(128) hf    g_Wv2[(size_t)2*DL*DL];
__device__ __align__(128) float g_bqkv[2*3*DL];
__device__ __align__(128) hf    g_Wo2[(size_t)2*DL*DL];
__device__ __align__(128) hf    g_Fw12[(size_t)2*FH*DL];
__device__ __align__(128) hf    g_Fw22[(size_t)2*DL*FH];
__device__ __align__(128) hf    g_Q2 [(size_t)MROWS*DL];
__device__ __align__(128) hf    g_K2 [(size_t)MROWS*DL];
__device__ __align__(128) hf    g_Vh [(size_t)MROWS*DL];
__device__ __align__(128) hf    g_O2 [(size_t)MROWS*DL];
__device__ __align__(128) hf    g_F12[(size_t)MROWS*FH];

// ---------------- helpers ----------------
__device__ __forceinline__ uint32_t smem_u32(const void* p){
    uint32_t a;
    asm("{ .reg .u64 t; cvta.to.shared.u64 t, %1; cvt.u32.u64 %0, t; }" : "=r"(a) : "l"(p));
    return a;
}
__device__ __forceinline__ void cp16(uint32_t s, const void* g){
    asm volatile("cp.async.cg.shared.global [%0], [%1], 16;" :: "r"(s), "l"(g));
}
#define CP_COMMIT() asm volatile("cp.async.commit_group;")
#define CP_WAIT0()  asm volatile("cp.async.wait_group 0;" ::: "memory")
#define CP_WAIT1()  asm volatile("cp.async.wait_group 1;" ::: "memory")
#define SWZ(o) ((o) ^ (((o)>>3)&0x70))

__device__ __forceinline__ void ldsm4(uint32_t &r0, uint32_t &r1, uint32_t &r2, uint32_t &r3, uint32_t a){
    asm volatile("ldmatrix.sync.aligned.m8n8.x4.shared.b16 {%0,%1,%2,%3}, [%4];"
                 : "=r"(r0), "=r"(r1), "=r"(r2), "=r"(r3) : "r"(a));
}
__device__ __forceinline__ void ldsm4t(uint32_t &r0, uint32_t &r1, uint32_t &r2, uint32_t &r3, uint32_t a){
    asm volatile("ldmatrix.sync.aligned.m8n8.x4.trans.shared.b16 {%0,%1,%2,%3}, [%4];"
                 : "=r"(r0), "=r"(r1), "=r"(r2), "=r"(r3) : "r"(a));
}
__device__ __forceinline__ void mma16816(float* d, const uint32_t* a, uint32_t b0, uint32_t b1){
    asm volatile("mma.sync.aligned.m16n8k16.row.col.f32.f16.f16.f32 "
                 "{%0,%1,%2,%3}, {%4,%5,%6,%7}, {%8,%9}, {%0,%1,%2,%3};"
                 : "+f"(d[0]), "+f"(d[1]), "+f"(d[2]), "+f"(d[3])
                 : "r"(a[0]), "r"(a[1]), "r"(a[2]), "r"(a[3]), "r"(b0), "r"(b1));
}
__device__ __forceinline__ uint32_t packh(hf a, hf b){
    hf2 t = __halves2half2(a, b);
    return *reinterpret_cast<uint32_t*>(&t);
}

// ================= mma.sync GEMM (dense layers) =================
// 256 threads, 8 warps (2m x 4n), warp tile 64x32, CTA 128x128, K-chunk 64,
// 3-stage ring, one barrier per chunk.
// modes: 0=fp32 out (ldc) + opt fp16 resid(ld DL), 1=fp16 out (ldc3) + opt fp16 resid,
//        2=fp16 per-head stride128, 3=fused QKV scatter (alpha on Q region only)
__global__ __launch_bounds__(256,2) void gemm_m(
    const hf* __restrict__ A, const hf* __restrict__ Bm,
    int Kp, int lda, int ldb,
    ll sA1, ll sA2, ll sB1, ll sB2, int batch2,
    int mode, int relu, float alpha,
    const float* __restrict__ bias, const hf* __restrict__ residh,
    float* __restrict__ Cf, int ldc,
    hf* __restrict__ C2, int ldc3,
    const hf* __restrict__ Bk2, const hf* __restrict__ Bv2)
{
    constexpr int STAGE = 32768;
    extern __shared__ char dyn[];
    const uint32_t sbase = (smem_u32(dyn) + 1023) & ~1023u;

    const int tid  = threadIdx.x;
    const int lane = tid & 31;
    const int wid  = tid >> 5;
    const int wm   = (wid >> 2) * 64;
    const int wn   = (wid & 3) * 32;

    const int z  = blockIdx.z;
    const int zb = z / batch2, zh = z - zb*batch2;
    const hf* Ab = A + zb*sA1 + zh*sA2 + (ll)blockIdx.y*128*lda;
    const hf* Bb;
    if (mode == 3){
        int reg = blockIdx.x >> 3;
        const hf* base = (reg==0) ? Bm : (reg==1) ? Bk2 : Bv2;
        Bb = base + (ll)(blockIdx.x & 7)*128*ldb;
    } else {
        Bb = Bm + zb*sB1 + zh*sB2 + (ll)blockIdx.x*128*ldb;
    }

    float acc[4][4][4];
    #pragma unroll
    for (int i=0;i<4;i++)
        #pragma unroll
        for (int j=0;j<4;j++)
            #pragma unroll
            for (int r=0;r<4;r++) acc[i][j][r] = 0.f;

    const int nchunk = Kp >> 6;

    #define LOAD_CHUNK(c, s) do { \
        const int k0_ = (c) << 6; \
        const uint32_t sa_ = sbase + (s)*STAGE; \
        const uint32_t sb_ = sa_ + 16384; \
        _Pragma("unroll") \
        for (int i_ = 0; i_ < 4; i_++){ \
            int idx_ = tid + i_*256; \
            int r_ = idx_>>3, j_ = idx_&7; \
            cp16(sa_ + SWZ(r_*128 + j_*16), Ab + (ll)r_*lda + k0_ + j_*8); \
        } \
        _Pragma("unroll") \
        for (int i_ = 0; i_ < 4; i_++){ \
            int idx_ = tid + i_*256; \
            int r_ = idx_>>3, j_ = idx_&7; \
            cp16(sb_ + SWZ(r_*128 + j_*16), Bb + (ll)r_*ldb + k0_ + j_*8); \
        } \
        CP_COMMIT(); \
    } while(0)

    LOAD_CHUNK(0, 0);
    if (nchunk > 1) LOAD_CHUNK(1, 1);

    const int la = lane & 15;
    const int lh = lane >> 4;

    int stage = 0;
    for (int c = 0; c < nchunk; c++){
        if (c + 1 < nchunk) { CP_WAIT1(); } else { CP_WAIT0(); }
        __syncthreads();
        if (c + 2 < nchunk){
            int s2 = stage + 2; if (s2 >= 3) s2 -= 3;
            LOAD_CHUNK(c + 2, s2);
        }
        const uint32_t sa = sbase + stage*STAGE;
        const uint32_t sb = sa + 16384;

        #pragma unroll
        for (int kk = 0; kk < 4; kk++){
            const int colb = kk*32 + lh*16;
            uint32_t af[4][4];
            #pragma unroll
            for (int i = 0; i < 4; i++){
                uint32_t o = (uint32_t)((wm + i*16 + la)*128 + colb);
                ldsm4(af[i][0], af[i][1], af[i][2], af[i][3], sa + SWZ(o));
            }
            uint32_t bfr[2][4];
            #pragma unroll
            for (int j = 0; j < 2; j++){
                uint32_t o = (uint32_t)((wn + j*16 + la)*128 + colb);
                ldsm4(bfr[j][0], bfr[j][1], bfr[j][2], bfr[j][3], sb + SWZ(o));
            }
            #pragma unroll
            for (int i = 0; i < 4; i++)
                #pragma unroll
                for (int jn = 0; jn < 4; jn++){
                    uint32_t b0 = (jn&1) ? bfr[jn>>1][1] : bfr[jn>>1][0];
                    uint32_t b1 = (jn&1) ? bfr[jn>>1][3] : bfr[jn>>1][2];
                    mma16816(acc[i][jn], af[i], b0, b1);
                }
        }
        if (++stage == 3) stage = 0;
    }
    #undef LOAD_CHUNK

    const int g  = lane >> 2;
    const int tg = (lane & 3) * 2;

    auto store2 = [&](int row, int cg, float v0, float v1){
        float aa = alpha;
        if (mode == 3 && cg >= 1024) aa = 1.f;
        if (bias){ v0 += __ldg(bias+cg); v1 += __ldg(bias+cg+1); }
        v0 *= aa; v1 *= aa;
        if (relu){ v0 = fmaxf(v0,0.f); v1 = fmaxf(v1,0.f); }
        if (mode <= 1){
            if (residh){
                hf2 rr = *(const hf2*)(residh + (ll)row*DL + cg);
                v0 += __half2float(rr.x); v1 += __half2float(rr.y);
            }
            if (mode == 0)
                *(float2*)(Cf + (ll)row*ldc + cg) = make_float2(v0, v1);
            else
                *(hf2*)(C2 + (ll)row*ldc3 + cg) = __floats2half2_rn(v0, v1);
        } else if (mode == 2){
            const int b = row>>10, t = row&1023, h = cg>>7, d0 = cg&127;
            const ll base = ((ll)(b*8+h)*1024 + t)*128 + d0;
            *(hf2*)(C2+base) = __floats2half2_rn(v0, v1);
        } else {
            const int region = cg >> 10;
            const int cin = cg & 1023;
            const int b = row>>10, t = row&1023, h = cin>>7, d0 = cin&127;
            const ll base = ((ll)(b*8+h)*1024 + t)*128 + d0;
            hf* tgt = (region==0) ? g_Q2 : (region==1) ? g_K2 : g_Vh;
            *(hf2*)(tgt+base) = __floats2half2_rn(v0, v1);
        }
    };

    #pragma unroll
    for (int i = 0; i < 4; i++){
        const int r0 = blockIdx.y*128 + wm + i*16 + g;
        #pragma unroll
        for (int jn = 0; jn < 4; jn++){
            const int cg = blockIdx.x*128 + wn + jn*8 + tg;
            store2(r0,     cg, acc[i][jn][0], acc[i][jn][1]);
            store2(r0 + 8, cg, acc[i][jn][2], acc[i][jn][3]);
        }
    }
}

// ================= flash attention v3 (unchanged from R13) ====
__global__ __launch_bounds__(128,2) void flash_k(
    const hf* __restrict__ Q2, const hf* __restrict__ K2,
    const hf* __restrict__ Vh, hf* __restrict__ O2)
{
    extern __shared__ char dyn[];
    const uint32_t sb = (smem_u32(dyn) + 1023) & ~1023u;
    const int tid = threadIdx.x, lane = tid & 31, wid = tid >> 5;
    const int qt = blockIdx.x, bh = blockIdx.y;
    const int b = bh >> 3, h = bh & 7;
    const int la = lane & 15, lh = lane >> 4;
    const int g = lane >> 2, tg = (lane & 3) * 2;

    const hf* Qg = Q2 + ((ll)bh*1024 + qt*64)*128;
    const hf* Kg = K2 + ((ll)bh*1024)*128;
    const hf* Vg = Vh + ((ll)bh*1024)*128;

    const uint32_t SQ = sb;
    const uint32_t SK0 = sb + 16384;
    const uint32_t SK1 = sb + 49152;
    const uint32_t SV  = sb + 81920;

    #define LQC(sb_, gp_) do{ _Pragma("unroll") \
        for (int i_=0;i_<4;i_++){ int idx_=tid+i_*128; int r_=idx_>>3, j_=idx_&7; \
            cp16((sb_)+SWZ(r_*128+j_*16), (gp_)+(ll)r_*128+j_*8); } }while(0)
    #define LKC(sb_, gp_) do{ _Pragma("unroll") \
        for (int i_=0;i_<8;i_++){ int idx_=tid+i_*128; int r_=idx_>>3, j_=idx_&7; \
            cp16((sb_)+SWZ(r_*128+j_*16), (gp_)+(ll)r_*128+j_*8); } }while(0)

    LQC(SQ,        Qg);
    LQC(SQ + 8192, Qg + 64);
    LKC(SK0,         Kg);
    LKC(SK0 + 16384, Kg + 64);
    CP_COMMIT();
    CP_WAIT0();
    __syncthreads();

    uint32_t qf[8][4];
    #pragma unroll
    for (int ks = 0; ks < 8; ks++){
        const int colb = (ks&3)*32 + lh*16;
        ldsm4(qf[ks][0], qf[ks][1], qf[ks][2], qf[ks][3],
              SQ + (ks>>2)*8192 + SWZ((wid*16+la)*128 + colb));
    }

    float oacc[8][2][4];
    #pragma unroll
    for (int j=0;j<8;j++)
        #pragma unroll
        for (int hh=0;hh<2;hh++)
            #pragma unroll
            for (int r=0;r<4;r++) oacc[j][hh][r] = 0.f;
    float mrow[2] = {-INFINITY, -INFINITY};
    float lrow[2] = {0.f, 0.f};

    for (int kt = 0; kt < 8; kt++){
        __syncthreads();
        CP_WAIT0();
        const int s = kt & 1;
        const uint32_t kbase = s ? SK1 : SK0;

        LKC(SV,         Vg + (ll)kt*128*128);
        LKC(SV + 16384, Vg + (ll)kt*128*128 + 64);
        CP_COMMIT();
        if (kt + 1 < 8){
            const uint32_t kb2 = s ? SK0 : SK1;
            LKC(kb2,         Kg + (ll)(kt+1)*128*128);
            LKC(kb2 + 16384, Kg + (ll)(kt+1)*128*128 + 64);
            CP_COMMIT();
        }

        float sacc[8][2][4];
        #pragma unroll
        for (int nb=0;nb<8;nb++)
            #pragma unroll
            for (int hh=0;hh<2;hh++)
                #pragma unroll
                for (int r=0;r<4;r++) sacc[nb][hh][r] = 0.f;

        #pragma unroll
        for (int ks = 0; ks < 8; ks++){
            const int colb = (ks&3)*32 + lh*16;
            #pragma unroll
            for (int nb = 0; nb < 8; nb++){
                uint32_t r0,r1,r2,r3;
                ldsm4(r0,r1,r2,r3,
                      kbase + (ks>>2)*16384 + SWZ((nb*16+la)*128 + colb));
                mma16816(sacc[nb][0], qf[ks], r0, r2);
                mma16816(sacc[nb][1], qf[ks], r1, r3);
            }
        }

        float pscale[2];
        #pragma unroll
        for (int r = 0; r < 2; r++){
            float mx = -INFINITY;
            #pragma unroll
            for (int nb=0;nb<8;nb++)
                #pragma unroll
                for (int hh=0;hh<2;hh++)
                    mx = fmaxf(mx, fmaxf(sacc[nb][hh][r*2], sacc[nb][hh][r*2+1]));
            mx = fmaxf(mx, __shfl_xor_sync(0xffffffffu, mx, 1));
            mx = fmaxf(mx, __shfl_xor_sync(0xffffffffu, mx, 2));
            const float mnew = fmaxf(mrow[r], mx);
            pscale[r] = __expf(mrow[r] - mnew);
            float ls = 0.f;
            #pragma unroll
            for (int nb=0;nb<8;nb++)
                #pragma unroll
                for (int hh=0;hh<2;hh++){
                    float p0 = __expf(sacc[nb][hh][r*2]   - mnew);
                    float p1 = __expf(sacc[nb][hh][r*2+1] - mnew);
                    sacc[nb][hh][r*2] = p0; sacc[nb][hh][r*2+1] = p1;
                    ls += p0 + p1;
                }
            ls += __shfl_xor_sync(0xffffffffu, ls, 1);
            ls += __shfl_xor_sync(0xffffffffu, ls, 2);
            lrow[r] = lrow[r]*pscale[r] + ls;
            mrow[r] = mnew;
        }
        #pragma unroll
        for (int r = 0; r < 2; r++){
            if (pscale[r] < 1.f){
                #pragma unroll
                for (int j=0;j<8;j++)
                    #pragma unroll
                    for (int hh=0;hh<2;hh++){
                        oacc[j][hh][r*2]   *= pscale[r];
                        oacc[j][hh][r*2+1] *= pscale[r];
                    }
            }
        }

        if (kt + 1 < 8) { CP_WAIT1(); } else { CP_WAIT0(); }

        #pragma unroll
        for (int nb = 0; nb < 8; nb++){
            uint32_t ahi[4];
            ahi[0]=packh(__float2half_rn(sacc[nb][0][0]), __float2half_rn(sacc[nb][0][1]));
            ahi[1]=packh(__float2half_rn(sacc[nb][0][2]), __float2half_rn(sacc[nb][0][3]));
            ahi[2]=packh(__float2half_rn(sacc[nb][1][0]), __float2half_rn(sacc[nb][1][1]));
            ahi[3]=packh(__float2half_rn(sacc[nb][1][2]), __float2half_rn(sacc[nb][1][3]));
            #pragma unroll
            for (int j = 0; j < 8; j++){
                uint32_t r0,r1,r2,r3;
                ldsm4t(r0,r1,r2,r3,
                       SV + (j>>2)*16384 + SWZ((nb*16+la)*128 + (j&3)*32 + lh*16));
                mma16816(oacc[j][0], ahi, r0, r1);
                mma16816(oacc[j][1], ahi, r2, r3);
            }
        }
    }
    #undef LQC
    #undef LKC

    #pragma unroll
    for (int r = 0; r < 2; r++){
        const int t = qt*64 + wid*16 + g + r*8;
        const float inv = 1.f / lrow[r];
        const ll base0 = ((ll)(b*1024 + t))*1024 + h*128;
        #pragma unroll
        for (int j = 0; j < 8; j++)
            #pragma unroll
            for (int hh = 0; hh < 2; hh++){
                const int d = j*16 + hh*8 + tg;
                *(hf2*)(O2 + base0 + d) =
                    __floats2half2_rn(oacc[j][hh][r*2]*inv, oacc[j][hh][r*2+1]*inv);
            }
    }
}

// ---------------- fp32 -> fp16 (float4 vectorized) ----------------
__global__ void conv_k(const float* __restrict__ in, hf* __restrict__ out, int n4)
{
    int i = blockIdx.x*256 + threadIdx.x;
    if (i >= n4) return;
    float4 v = ((const float4*)in)[i];
    hf2 a = __floats2half2_rn(v.x, v.y);
    hf2 b = __floats2half2_rn(v.z, v.w);
    uint32_t ua = *(uint32_t*)&a, ub = *(uint32_t*)&b;
    ((uint2*)out)[i] = make_uint2(ua, ub);
}

// ---------------- bias concat for fused QKV ----------------
__global__ void catb_k(const float* __restrict__ a, const float* __restrict__ b,
                       const float* __restrict__ c, float* __restrict__ o)
{
    int i = blockIdx.x*256 + threadIdx.x;
    if (i >= 2*3*DL) return;
    int l = i / (3*DL), j = i % (3*DL);
    float v = (j < DL) ? a[l*DL + j] : (j < 2*DL) ? b[l*DL + j-DL] : c[l*DL + j-2*DL];
    o[i] = v;
}

// ---------------- LayerNorm (fp16 in) -> fp16, ld 1024 ----------------
__global__ __launch_bounds__(128) void layernorm_k(
    const hf* __restrict__ X, hf* __restrict__ Y2,
    const float* __restrict__ g, const float* __restrict__ b)
{
    const int row  = blockIdx.x*4 + (threadIdx.x >> 5);
    const int lane = threadIdx.x & 31;
    const hf* p = X + (ll)row*DL;

    hf2 v[16]; float s = 0.f;
    #pragma unroll
    for (int i=0;i<4;i++){
        uint4 u = *(const uint4*)(p + (i*32+lane)*8);
        hf2* hv = (hf2*)&u;
        #pragma unroll
        for (int j=0;j<4;j++){
            v[i*4+j] = hv[j];
            float2 f = __half22float2(hv[j]);
            s += f.x + f.y;
        }
    }
    #pragma unroll
    for (int o=16;o>0;o>>=1) s += __shfl_xor_sync(0xffffffffu, s, o);
    const float m = s * (1.f/DL);
    float vs = 0.f;
    #pragma unroll
    for (int k=0;k<16;k++){
        float2 f = __half22float2(v[k]);
        float dx = f.x - m, dy = f.y - m;
        vs += dx*dx + dy*dy;
    }
    #pragma unroll
    for (int o=16;o>0;o>>=1) vs += __shfl_xor_sync(0xffffffffu, vs, o);
    const float r = rsqrtf(vs*(1.f/DL) + 1e-12f);

    hf* q = Y2 + (ll)row*DL;
    #pragma unroll
    for (int i=0;i<4;i++){
        const int c = (i*32+lane)*8;
        uint4 uo;
        hf2* ho = (hf2*)&uo;
        #pragma unroll
        for (int j=0;j<4;j++){
            float2 f  = __half22float2(v[i*4+j]);
            float2 gg = *(const float2*)(g + c + j*2);
            float2 bb = *(const float2*)(b + c + j*2);
            float o0 = (f.x - m)*r*gg.x + bb.x;
            float o1 = (f.y - m)*r*gg.y + bb.y;
            ho[j] = __floats2half2_rn(o0, o1);
        }
        *(uint4*)(q + c) = uo;
    }
}

// ---------------- host ----------------
static void gm(const hf*A,const hf*B,int M,int N,int Kp,int lda,int ldb,
    ll sA1,ll sA2,ll sB1,ll sB2,int batch,int batch2,int mode,int relu,float alpha,
    const float*bias,const hf*residh,float*Cf,int ldc,hf*C2,int ldc3,
    const hf*Bk2=nullptr,const hf*Bv2=nullptr)
{
    dim3 g(N/128, M/128, batch);
    gemm_m<<<g,256,99328>>>(A,B,Kp,lda,ldb,sA1,sA2,sB1,sB2,batch2,
        mode,relu,alpha,bias,residh,Cf,ldc,C2,ldc3,Bk2,Bv2);
}
static void conv(const float* in, hf* out, int n){
    conv_k<<<(n/4+255)/256,256>>>(in, out, n/4);
}

extern "C" void kernel_launch(void* const* d_in, const int* in_sizes, int n_in,
                              void* d_out, int out_size)
{
    (void)in_sizes; (void)n_in; (void)out_size;
    const float* x   = (const float*)d_in[0];
    const float* W1  = (const float*)d_in[1];
    const float* b1  = (const float*)d_in[2];
    const float* W2  = (const float*)d_in[3];
    const float* b2  = (const float*)d_in[4];
    const float* ln1g= (const float*)d_in[5];
    const float* ln1b= (const float*)d_in[6];
    const float* ln2g= (const float*)d_in[7];
    const float* ln2b= (const float*)d_in[8];
    const float* Wq  = (const float*)d_in[9];
    const float* bq  = (const float*)d_in[10];
    const float* Wk  = (const float*)d_in[11];
    const float* bk  = (const float*)d_in[12];
    const float* Wv  = (const float*)d_in[13];
    const float* bv  = (const float*)d_in[14];
    const float* Wo  = (const float*)d_in[15];
    const float* bo  = (const float*)d_in[16];
    const float* Fw1 = (const float*)d_in[17];
    const float* Fb1 = (const float*)d_in[18];
    const float* Fw2 = (const float*)d_in[19];
    const float* Fb2 = (const float*)d_in[20];
    float* out = (float*)d_out;

    cudaFuncSetAttribute(gemm_m, cudaFuncAttributeMaxDynamicSharedMemorySize, 99328);
    cudaFuncSetAttribute(flash_k, cudaFuncAttributeMaxDynamicSharedMemorySize, 115712);

    hf *x2,*W12,*H12,*W22,*X,*Hn2,*Wq2,*Wk2,*Wv2,*Wo2,*Fw12,*Fw22,*Q2,*K2,*Vh,*O2,*F12;
    float *bqkv;
    cudaGetSymbolAddress((void**)&x2 , g_x2 );
    cudaGetSymbolAddress((void**)&W12, g_W12);
    cudaGetSymbolAddress((void**)&H12, g_H12);
    cudaGetSymbolAddress((void**)&W22, g_W22);
    cudaGetSymbolAddress((void**)&X  , g_X  );
    cudaGetSymbolAddress((void**)&Hn2, g_Hn2);
    cudaGetSymbolAddress((void**)&Wq2, g_Wq2);
    cudaGetSymbolAddress((void**)&Wk2, g_Wk2);
    cudaGetSymbolAddress((void**)&Wv2, g_Wv2);
    cudaGetSymbolAddress((void**)&bqkv, g_bqkv);
    cudaGetSymbolAddress((void**)&Wo2, g_Wo2);
    cudaGetSymbolAddress((void**)&Fw12, g_Fw12);
    cudaGetSymbolAddress((void**)&Fw22, g_Fw22);
    cudaGetSymbolAddress((void**)&Q2 , g_Q2 );
    cudaGetSymbolAddress((void**)&K2 , g_K2 );
    cudaGetSymbolAddress((void**)&Vh , g_Vh );
    cudaGetSymbolAddress((void**)&O2 , g_O2 );
    cudaGetSymbolAddress((void**)&F12, g_F12);

    const float scl = 0.08838834764831845f; // 128^-0.5

    // ---- all weight conversions upfront ----
    conv(x,   x2,  MROWS*DL);
    conv(W1,  W12, DFF*DL);
    conv(W2,  W22, DL*DFF);
    conv(Wq,  Wq2, 2*DL*DL);
    conv(Wk,  Wk2, 2*DL*DL);
    conv(Wv,  Wv2, 2*DL*DL);
    conv(Wo,  Wo2, 2*DL*DL);
    conv(Fw1, Fw12, 2*FH*DL);
    conv(Fw2, Fw22, 2*DL*FH);
    catb_k<<<24,256>>>(bq, bk, bv, bqkv);

    // ---- downsample ----
    gm(x2, W12, MROWS, DFF, DL, DL, DL, 0,0,0,0, 1,1,
       1,1,1.f, b1, nullptr, nullptr,0, H12, DFF);
    gm(H12, W22, MROWS, DL, DFF, DFF, DFF, 0,0,0,0, 1,1,
       1,0,1.f, b2, nullptr, nullptr,0, X, DL);

    for (int l = 0; l < 2; l++){
        const ll lw = (ll)l*DL*DL;

        layernorm_k<<<MROWS/4,128>>>(X, Hn2, ln1g+l*DL, ln1b+l*DL);
        gm(Hn2, Wq2+lw, MROWS, 3*DL, DL, DL, DL, 0,0,0,0, 1,1,
           3,0,scl, bqkv + l*3*DL, nullptr, nullptr,0, nullptr, 0,
           Wk2+lw, Wv2+lw);

        flash_k<<<dim3(16,64),128,115712>>>(Q2, K2, Vh, O2);

        // X = X + O @ Wo^T + bo  (fp16 trunk)
        gm(O2, Wo2+lw, MROWS, DL, DL, DL, DL, 0,0,0,0, 1,1,
           1,0,1.f, bo+l*DL, X, nullptr,0, X, DL);

        layernorm_k<<<MROWS/4,128>>>(X, Hn2, ln2g+l*DL, ln2b+l*DL);
        gm(Hn2, Fw12+(ll)l*FH*DL, MROWS, FH, DL, DL, DL, 0,0,0,0, 1,1,
           1,1,1.f, Fb1+l*FH, nullptr, nullptr,0, F12, FH);
        if (l == 0){
            gm(F12, Fw22, MROWS, DL, FH, FH, FH, 0,0,0,0, 1,1,
               1,0,1.f, Fb2, X, nullptr,0, X, DL);
        } else {
            gm(F12, Fw22+(ll)DL*FH, MROWS, DL, FH, FH, FH, 0,0,0,0, 1,1,
               0,0,1.f, Fb2+DL, X, out, DL, nullptr,0);
        }
    }
}

// round 16
// speedup vs baseline: 1.0419x; 1.0419x over previous
#include <cuda_runtime.h>
#include <cuda_fp16.h>
#include <cstdint>
#include <math.h>
typedef long long ll;
typedef __half hf;
typedef __half2 hf2;

#define B_ 8
#define T_ 1024
#define DL 1024
#define NH 8
#define DKH 128
#define DFF 2048
#define FH 256
#define MROWS 8192

// ---------------- device scratch ----------------
__device__ __align__(128) hf    g_x2 [(size_t)MROWS*DL];
__device__ __align__(128) hf    g_W12[(size_t)DFF*DL];
__device__ __align__(128) hf    g_H12[(size_t)MROWS*DFF];
__device__ __align__(128) hf    g_W22[(size_t)DL*DFF];
__device__ __align__(128) float g_X  [(size_t)MROWS*DL];
__device__ __align__(128) hf    g_Hn2[(size_t)MROWS*DL];
__device__ __align__(128) hf    g_Wq2[(size_t)2*DL*DL];
__device__ __align__(128) hf    g_Wk2[(size_t)2*DL*DL];
__device__ __align__(128) hf    g_Wv2[(size_t)2*DL*DL];
__device__ __align__(128) hf    g_Wo2[(size_t)2*DL*DL];
__device__ __align__(128) hf    g_Fw12[(size_t)2*FH*DL];
__device__ __align__(128) hf    g_Fw22[(size_t)2*DL*FH];
__device__ __align__(128) hf    g_Q2 [(size_t)MROWS*DL];
__device__ __align__(128) hf    g_K2 [(size_t)MROWS*DL];
__device__ __align__(128) hf    g_Vh [(size_t)MROWS*DL];
__device__ __align__(128) hf    g_O2 [(size_t)MROWS*DL];
__device__ __align__(128) hf    g_F12[(size_t)MROWS*FH];

// ---------------- helpers ----------------
__device__ __forceinline__ uint32_t smem_u32(const void* p){
    uint32_t a;
    asm("{ .reg .u64 t; cvta.to.shared.u64 t, %1; cvt.u32.u64 %0, t; }" : "=r"(a) : "l"(p));
    return a;
}
__device__ __forceinline__ void cp16(uint32_t s, const void* g){
    asm volatile("cp.async.cg.shared.global [%0], [%1], 16;" :: "r"(s), "l"(g));
}
#define CP_COMMIT() asm volatile("cp.async.commit_group;")
#define CP_WAIT0()  asm volatile("cp.async.wait_group 0;" ::: "memory")
#define CP_WAIT1()  asm volatile("cp.async.wait_group 1;" ::: "memory")
#define SWZ(o) ((o) ^ (((o)>>3)&0x70))

__device__ __forceinline__ void ldsm4(uint32_t &r0, uint32_t &r1, uint32_t &r2, uint32_t &r3, uint32_t a){
    asm volatile("ldmatrix.sync.aligned.m8n8.x4.shared.b16 {%0,%1,%2,%3}, [%4];"
                 : "=r"(r0), "=r"(r1), "=r"(r2), "=r"(r3) : "r"(a));
}
__device__ __forceinline__ void ldsm4t(uint32_t &r0, uint32_t &r1, uint32_t &r2, uint32_t &r3, uint32_t a){
    asm volatile("ldmatrix.sync.aligned.m8n8.x4.trans.shared.b16 {%0,%1,%2,%3}, [%4];"
                 : "=r"(r0), "=r"(r1), "=r"(r2), "=r"(r3) : "r"(a));
}
__device__ __forceinline__ void mma16816(float* d, const uint32_t* a, uint32_t b0, uint32_t b1){
    asm volatile("mma.sync.aligned.m16n8k16.row.col.f32.f16.f16.f32 "
                 "{%0,%1,%2,%3}, {%4,%5,%6,%7}, {%8,%9}, {%0,%1,%2,%3};"
                 : "+f"(d[0]), "+f"(d[1]), "+f"(d[2]), "+f"(d[3])
                 : "r"(a[0]), "r"(a[1]), "r"(a[2]), "r"(a[3]), "r"(b0), "r"(b1));
}
__device__ __forceinline__ uint32_t packh(hf a, hf b){
    hf2 t = __halves2half2(a, b);
    return *reinterpret_cast<uint32_t*>(&t);
}

// ================= mma.sync GEMM (dense layers) =================
// 256 threads, 8 warps (2m x 4n), warp tile 64x32, CTA 128x128, K-chunk 64,
// 3-stage ring, one barrier per chunk.
// modes: 0=fp32 out(+fp32 resid), 1=fp16 row-major (ldc3), 2=fp16 per-head stride128,
//        3=fused QKV scatter (B and bias selected by N-region; alpha on Q region only)
__global__ __launch_bounds__(256,2) void gemm_m(
    const hf* __restrict__ A, const hf* __restrict__ Bm,
    int Kp, int lda, int ldb,
    int mode, int relu, float alpha,
    const float* __restrict__ bias, const float* __restrict__ resid,
    float* __restrict__ Cf, int ldc,
    hf* __restrict__ C2, int ldc3,
    const hf* __restrict__ Bk2, const hf* __restrict__ Bv2,
    const float* __restrict__ biasK, const float* __restrict__ biasV)
{
    constexpr int STAGE = 32768;
    extern __shared__ char dyn[];
    const uint32_t sbase = (smem_u32(dyn) + 1023) & ~1023u;

    const int tid  = threadIdx.x;
    const int lane = tid & 31;
    const int wid  = tid >> 5;
    const int wm   = (wid >> 2) * 64;
    const int wn   = (wid & 3) * 32;

    const hf* Ab = A + (ll)blockIdx.y*128*lda;
    const hf* Bb;
    if (mode == 3){
        int reg = blockIdx.x >> 3;
        const hf* base = (reg==0) ? Bm : (reg==1) ? Bk2 : Bv2;
        Bb = base + (ll)(blockIdx.x & 7)*128*ldb;
    } else {
        Bb = Bm + (ll)blockIdx.x*128*ldb;
    }

    float acc[4][4][4];
    #pragma unroll
    for (int i=0;i<4;i++)
        #pragma unroll
        for (int j=0;j<4;j++)
            #pragma unroll
            for (int r=0;r<4;r++) acc[i][j][r] = 0.f;

    const int nchunk = Kp >> 6;

    #define LOAD_CHUNK(c, s) do { \
        const int k0_ = (c) << 6; \
        const uint32_t sa_ = sbase + (s)*STAGE; \
        const uint32_t sb_ = sa_ + 16384; \
        _Pragma("unroll") \
        for (int i_ = 0; i_ < 4; i_++){ \
            int idx_ = tid + i_*256; \
            int r_ = idx_>>3, j_ = idx_&7; \
            cp16(sa_ + SWZ(r_*128 + j_*16), Ab + (ll)r_*lda + k0_ + j_*8); \
        } \
        _Pragma("unroll") \
        for (int i_ = 0; i_ < 4; i_++){ \
            int idx_ = tid + i_*256; \
            int r_ = idx_>>3, j_ = idx_&7; \
            cp16(sb_ + SWZ(r_*128 + j_*16), Bb + (ll)r_*ldb + k0_ + j_*8); \
        } \
        CP_COMMIT(); \
    } while(0)

    LOAD_CHUNK(0, 0);
    if (nchunk > 1) LOAD_CHUNK(1, 1);

    const int la = lane & 15;
    const int lh = lane >> 4;

    int stage = 0;
    for (int c = 0; c < nchunk; c++){
        if (c + 1 < nchunk) { CP_WAIT1(); } else { CP_WAIT0(); }
        __syncthreads();
        if (c + 2 < nchunk){
            int s2 = stage + 2; if (s2 >= 3) s2 -= 3;
            LOAD_CHUNK(c + 2, s2);
        }
        const uint32_t sa = sbase + stage*STAGE;
        const uint32_t sb = sa + 16384;

        #pragma unroll
        for (int kk = 0; kk < 4; kk++){
            const int colb = kk*32 + lh*16;
            uint32_t af[4][4];
            #pragma unroll
            for (int i = 0; i < 4; i++){
                uint32_t o = (uint32_t)((wm + i*16 + la)*128 + colb);
                ldsm4(af[i][0], af[i][1], af[i][2], af[i][3], sa + SWZ(o));
            }
            uint32_t bfr[2][4];
            #pragma unroll
            for (int j = 0; j < 2; j++){
                uint32_t o = (uint32_t)((wn + j*16 + la)*128 + colb);
                ldsm4(bfr[j][0], bfr[j][1], bfr[j][2], bfr[j][3], sb + SWZ(o));
            }
            #pragma unroll
            for (int i = 0; i < 4; i++)
                #pragma unroll
                for (int jn = 0; jn < 4; jn++){
                    uint32_t b0 = (jn&1) ? bfr[jn>>1][1] : bfr[jn>>1][0];
                    uint32_t b1 = (jn&1) ? bfr[jn>>1][3] : bfr[jn>>1][2];
                    mma16816(acc[i][jn], af[i], b0, b1);
                }
        }
        if (++stage == 3) stage = 0;
    }
    #undef LOAD_CHUNK

    const int g  = lane >> 2;
    const int tg = (lane & 3) * 2;

    auto store2 = [&](int row, int cg, float v0, float v1){
        if (mode == 3){
            const int region = cg >> 10;
            const int cin = cg & 1023;
            const float* bp = (region==0) ? bias : (region==1) ? biasK : biasV;
            v0 += __ldg(bp+cin); v1 += __ldg(bp+cin+1);
            if (region == 0){ v0 *= alpha; v1 *= alpha; }
            const int b = row>>10, t = row&1023, h = cin>>7, d0 = cin&127;
            const ll base = ((ll)(b*8+h)*1024 + t)*128 + d0;
            hf* tgt = (region==0) ? g_Q2 : (region==1) ? g_K2 : g_Vh;
            *(hf2*)(tgt+base) = __floats2half2_rn(v0, v1);
            return;
        }
        if (bias){ v0 += __ldg(bias+cg); v1 += __ldg(bias+cg+1); }
        v0 *= alpha; v1 *= alpha;
        if (relu){ v0 = fmaxf(v0,0.f); v1 = fmaxf(v1,0.f); }
        if (mode == 0){
            const ll base = (ll)row*ldc + cg;
            float2 w = make_float2(v0, v1);
            if (resid){
                float2 rr = *(const float2*)(resid + base);
                w.x += rr.x; w.y += rr.y;
            }
            *(float2*)(Cf + base) = w;
        } else if (mode == 1){
            const ll base = (ll)row*ldc3 + cg;
            *(hf2*)(C2+base) = __floats2half2_rn(v0, v1);
        } else { // mode 2
            const int b = row>>10, t = row&1023, h = cg>>7, d0 = cg&127;
            const ll base = ((ll)(b*8+h)*1024 + t)*128 + d0;
            *(hf2*)(C2+base) = __floats2half2_rn(v0, v1);
        }
    };

    #pragma unroll
    for (int i = 0; i < 4; i++){
        const int r0 = blockIdx.y*128 + wm + i*16 + g;
        #pragma unroll
        for (int jn = 0; jn < 4; jn++){
            const int cg = blockIdx.x*128 + wn + jn*8 + tg;
            store2(r0,     cg, acc[i][jn][0], acc[i][jn][1]);
            store2(r0 + 8, cg, acc[i][jn][2], acc[i][jn][3]);
        }
    }
}

// ================= flash attention v3 (R13) ====
// grid (16 qt, 64 bh), 128 thr, 2 CTA/SM; Q in registers; V single-buffered.
__global__ __launch_bounds__(128,2) void flash_k(
    const hf* __restrict__ Q2, const hf* __restrict__ K2,
    const hf* __restrict__ Vh, hf* __restrict__ O2)
{
    extern __shared__ char dyn[];
    const uint32_t sb = (smem_u32(dyn) + 1023) & ~1023u;
    const int tid = threadIdx.x, lane = tid & 31, wid = tid >> 5;
    const int qt = blockIdx.x, bh = blockIdx.y;
    const int b = bh >> 3, h = bh & 7;
    const int la = lane & 15, lh = lane >> 4;
    const int g = lane >> 2, tg = (lane & 3) * 2;

    const hf* Qg = Q2 + ((ll)bh*1024 + qt*64)*128;
    const hf* Kg = K2 + ((ll)bh*1024)*128;
    const hf* Vg = Vh + ((ll)bh*1024)*128;

    const uint32_t SQ = sb;
    const uint32_t SK0 = sb + 16384;
    const uint32_t SK1 = sb + 49152;
    const uint32_t SV  = sb + 81920;

    #define LQC(sb_, gp_) do{ _Pragma("unroll") \
        for (int i_=0;i_<4;i_++){ int idx_=tid+i_*128; int r_=idx_>>3, j_=idx_&7; \
            cp16((sb_)+SWZ(r_*128+j_*16), (gp_)+(ll)r_*128+j_*8); } }while(0)
    #define LKC(sb_, gp_) do{ _Pragma("unroll") \
        for (int i_=0;i_<8;i_++){ int idx_=tid+i_*128; int r_=idx_>>3, j_=idx_&7; \
            cp16((sb_)+SWZ(r_*128+j_*16), (gp_)+(ll)r_*128+j_*8); } }while(0)

    LQC(SQ,        Qg);
    LQC(SQ + 8192, Qg + 64);
    LKC(SK0,         Kg);
    LKC(SK0 + 16384, Kg + 64);
    CP_COMMIT();
    CP_WAIT0();
    __syncthreads();

    uint32_t qf[8][4];
    #pragma unroll
    for (int ks = 0; ks < 8; ks++){
        const int colb = (ks&3)*32 + lh*16;
        ldsm4(qf[ks][0], qf[ks][1], qf[ks][2], qf[ks][3],
              SQ + (ks>>2)*8192 + SWZ((wid*16+la)*128 + colb));
    }

    float oacc[8][2][4];
    #pragma unroll
    for (int j=0;j<8;j++)
        #pragma unroll
        for (int hh=0;hh<2;hh++)
            #pragma unroll
            for (int r=0;r<4;r++) oacc[j][hh][r] = 0.f;
    float mrow[2] = {-INFINITY, -INFINITY};
    float lrow[2] = {0.f, 0.f};

    for (int kt = 0; kt < 8; kt++){
        __syncthreads();
        CP_WAIT0();
        const int s = kt & 1;
        const uint32_t kbase = s ? SK1 : SK0;

        LKC(SV,         Vg + (ll)kt*128*128);
        LKC(SV + 16384, Vg + (ll)kt*128*128 + 64);
        CP_COMMIT();
        if (kt + 1 < 8){
            const uint32_t kb2 = s ? SK0 : SK1;
            LKC(kb2,         Kg + (ll)(kt+1)*128*128);
            LKC(kb2 + 16384, Kg + (ll)(kt+1)*128*128 + 64);
            CP_COMMIT();
        }

        float sacc[8][2][4];
        #pragma unroll
        for (int nb=0;nb<8;nb++)
            #pragma unroll
            for (int hh=0;hh<2;hh++)
                #pragma unroll
                for (int r=0;r<4;r++) sacc[nb][hh][r] = 0.f;

        #pragma unroll
        for (int ks = 0; ks < 8; ks++){
            const int colb = (ks&3)*32 + lh*16;
            #pragma unroll
            for (int nb = 0; nb < 8; nb++){
                uint32_t r0,r1,r2,r3;
                ldsm4(r0,r1,r2,r3,
                      kbase + (ks>>2)*16384 + SWZ((nb*16+la)*128 + colb));
                mma16816(sacc[nb][0], qf[ks], r0, r2);
                mma16816(sacc[nb][1], qf[ks], r1, r3);
            }
        }

        float pscale[2];
        #pragma unroll
        for (int r = 0; r < 2; r++){
            float mx = -INFINITY;
            #pragma unroll
            for (int nb=0;nb<8;nb++)
                #pragma unroll
                for (int hh=0;hh<2;hh++)
                    mx = fmaxf(mx, fmaxf(sacc[nb][hh][r*2], sacc[nb][hh][r*2+1]));
            mx = fmaxf(mx, __shfl_xor_sync(0xffffffffu, mx, 1));
            mx = fmaxf(mx, __shfl_xor_sync(0xffffffffu, mx, 2));
            const float mnew = fmaxf(mrow[r], mx);
            pscale[r] = __expf(mrow[r] - mnew);
            float ls = 0.f;
            #pragma unroll
            for (int nb=0;nb<8;nb++)
                #pragma unroll
                for (int hh=0;hh<2;hh++){
                    float p0 = __expf(sacc[nb][hh][r*2]   - mnew);
                    float p1 = __expf(sacc[nb][hh][r*2+1] - mnew);
                    sacc[nb][hh][r*2] = p0; sacc[nb][hh][r*2+1] = p1;
                    ls += p0 + p1;
                }
            ls += __shfl_xor_sync(0xffffffffu, ls, 1);
            ls += __shfl_xor_sync(0xffffffffu, ls, 2);
            lrow[r] = lrow[r]*pscale[r] + ls;
            mrow[r] = mnew;
        }
        #pragma unroll
        for (int r = 0; r < 2; r++){
            if (pscale[r] < 1.f){
                #pragma unroll
                for (int j=0;j<8;j++)
                    #pragma unroll
                    for (int hh=0;hh<2;hh++){
                        oacc[j][hh][r*2]   *= pscale[r];
                        oacc[j][hh][r*2+1] *= pscale[r];
                    }
            }
        }

        if (kt + 1 < 8) { CP_WAIT1(); } else { CP_WAIT0(); }

        #pragma unroll
        for (int nb = 0; nb < 8; nb++){
            uint32_t ahi[4];
            ahi[0]=packh(__float2half_rn(sacc[nb][0][0]), __float2half_rn(sacc[nb][0][1]));
            ahi[1]=packh(__float2half_rn(sacc[nb][0][2]), __float2half_rn(sacc[nb][0][3]));
            ahi[2]=packh(__float2half_rn(sacc[nb][1][0]), __float2half_rn(sacc[nb][1][1]));
            ahi[3]=packh(__float2half_rn(sacc[nb][1][2]), __float2half_rn(sacc[nb][1][3]));
            #pragma unroll
            for (int j = 0; j < 8; j++){
                uint32_t r0,r1,r2,r3;
                ldsm4t(r0,r1,r2,r3,
                       SV + (j>>2)*16384 + SWZ((nb*16+la)*128 + (j&3)*32 + lh*16));
                mma16816(oacc[j][0], ahi, r0, r1);
                mma16816(oacc[j][1], ahi, r2, r3);
            }
        }
    }
    #undef LQC
    #undef LKC

    #pragma unroll
    for (int r = 0; r < 2; r++){
        const int t = qt*64 + wid*16 + g + r*8;
        const float inv = 1.f / lrow[r];
        const ll base0 = ((ll)(b*1024 + t))*1024 + h*128;
        #pragma unroll
        for (int j = 0; j < 8; j++)
            #pragma unroll
            for (int hh = 0; hh < 2; hh++){
                const int d = j*16 + hh*8 + tg;
                *(hf2*)(O2 + base0 + d) =
                    __floats2half2_rn(oacc[j][hh][r*2]*inv, oacc[j][hh][r*2+1]*inv);
            }
    }
}

// ---------------- fused multi-tensor fp32 -> fp16 conversion ----------------
#define NSEG 9
struct ConvArgs {
    const float* in[NSEG];
    hf*          out[NSEG];
    int          off[NSEG+1];   // cumulative n4 offsets
};
__global__ void convall_k(ConvArgs a)
{
    int i = blockIdx.x*256 + threadIdx.x;
    if (i >= a.off[NSEG]) return;
    int s = 0;
    #pragma unroll
    for (int k = 0; k < NSEG-1; k++) s += (i >= a.off[k+1]);
    const int j = i - a.off[s];
    float4 v = ((const float4*)a.in[s])[j];
    hf2 p0 = __floats2half2_rn(v.x, v.y);
    hf2 p1 = __floats2half2_rn(v.z, v.w);
    ((uint2*)a.out[s])[j] = make_uint2(*(uint32_t*)&p0, *(uint32_t*)&p1);
}

// ---------------- LayerNorm (fp32 in) -> fp16, ld 1024 ----------------
__global__ __launch_bounds__(128) void layernorm_k(
    const float* __restrict__ X, hf* __restrict__ Y2,
    const float* __restrict__ g, const float* __restrict__ b)
{
    const int row  = blockIdx.x*4 + (threadIdx.x >> 5);
    const int lane = threadIdx.x & 31;
    const float* p = X + (ll)row*DL;
    float4 v[8]; float s = 0.f;
    #pragma unroll
    for (int i=0;i<8;i++){
        v[i] = *(const float4*)(p + (i*32+lane)*4);
        s += v[i].x + v[i].y + v[i].z + v[i].w;
    }
    #pragma unroll
    for (int o=16;o>0;o>>=1) s += __shfl_xor_sync(0xffffffffu, s, o);
    const float m = s * (1.f/DL);
    float vs = 0.f;
    #pragma unroll
    for (int i=0;i<8;i++){
        float dx=v[i].x-m, dy=v[i].y-m, dz=v[i].z-m, dw=v[i].w-m;
        vs += dx*dx + dy*dy + dz*dz + dw*dw;
    }
    #pragma unroll
    for (int o=16;o>0;o>>=1) vs += __shfl_xor_sync(0xffffffffu, vs, o);
    const float r = rsqrtf(vs*(1.f/DL) + 1e-12f);
    hf* q = Y2 + (ll)row*DL;
    #pragma unroll
    for (int i=0;i<8;i++){
        int c = (i*32+lane)*4;
        float4 gg = *(const float4*)(g + c);
        float4 bb = *(const float4*)(b + c);
        float o0=(v[i].x-m)*r*gg.x+bb.x, o1=(v[i].y-m)*r*gg.y+bb.y;
        float o2=(v[i].z-m)*r*gg.z+bb.z, o3=(v[i].w-m)*r*gg.w+bb.w;
        *(hf2*)(q+c)   = __floats2half2_rn(o0, o1);
        *(hf2*)(q+c+2) = __floats2half2_rn(o2, o3);
    }
}

// ---------------- host ----------------
static void gm(const hf*A,const hf*B,int M,int N,int Kp,int lda,int ldb,
    int mode,int relu,float alpha,
    const float*bias,const float*resid,float*Cf,int ldc,hf*C2,int ldc3,
    const hf*Bk2=nullptr,const hf*Bv2=nullptr,
    const float*biasK=nullptr,const float*biasV=nullptr)
{
    dim3 g(N/128, M/128, 1);
    gemm_m<<<g,256,99328>>>(A,B,Kp,lda,ldb,
        mode,relu,alpha,bias,resid,Cf,ldc,C2,ldc3,Bk2,Bv2,biasK,biasV);
}

extern "C" void kernel_launch(void* const* d_in, const int* in_sizes, int n_in,
                              void* d_out, int out_size)
{
    (void)in_sizes; (void)n_in; (void)out_size;
    const float* x   = (const float*)d_in[0];
    const float* W1  = (const float*)d_in[1];
    const float* b1  = (const float*)d_in[2];
    const float* W2  = (const float*)d_in[3];
    const float* b2  = (const float*)d_in[4];
    const float* ln1g= (const float*)d_in[5];
    const float* ln1b= (const float*)d_in[6];
    const float* ln2g= (const float*)d_in[7];
    const float* ln2b= (const float*)d_in[8];
    const float* Wq  = (const float*)d_in[9];
    const float* bq  = (const float*)d_in[10];
    const float* Wk  = (const float*)d_in[11];
    const float* bk  = (const float*)d_in[12];
    const float* Wv  = (const float*)d_in[13];
    const float* bv  = (const float*)d_in[14];
    const float* Wo  = (const float*)d_in[15];
    const float* bo  = (const float*)d_in[16];
    const float* Fw1 = (const float*)d_in[17];
    const float* Fb1 = (const float*)d_in[18];
    const float* Fw2 = (const float*)d_in[19];
    const float* Fb2 = (const float*)d_in[20];
    float* out = (float*)d_out;

    cudaFuncSetAttribute(gemm_m, cudaFuncAttributeMaxDynamicSharedMemorySize, 99328);
    cudaFuncSetAttribute(flash_k, cudaFuncAttributeMaxDynamicSharedMemorySize, 115712);

    hf *x2,*W12,*H12,*W22,*Hn2,*Wq2,*Wk2,*Wv2,*Wo2,*Fw12,*Fw22,*Q2,*K2,*Vh,*O2,*F12;
    float *X;
    cudaGetSymbolAddress((void**)&x2 , g_x2 );
    cudaGetSymbolAddress((void**)&W12, g_W12);
    cudaGetSymbolAddress((void**)&H12, g_H12);
    cudaGetSymbolAddress((void**)&W22, g_W22);
    cudaGetSymbolAddress((void**)&X  , g_X  );
    cudaGetSymbolAddress((void**)&Hn2, g_Hn2);
    cudaGetSymbolAddress((void**)&Wq2, g_Wq2);
    cudaGetSymbolAddress((void**)&Wk2, g_Wk2);
    cudaGetSymbolAddress((void**)&Wv2, g_Wv2);
    cudaGetSymbolAddress((void**)&Wo2, g_Wo2);
    cudaGetSymbolAddress((void**)&Fw12, g_Fw12);
    cudaGetSymbolAddress((void**)&Fw22, g_Fw22);
    cudaGetSymbolAddress((void**)&Q2 , g_Q2 );
    cudaGetSymbolAddress((void**)&K2 , g_K2 );
    cudaGetSymbolAddress((void**)&Vh , g_Vh );
    cudaGetSymbolAddress((void**)&O2 , g_O2 );
    cudaGetSymbolAddress((void**)&F12, g_F12);

    const float scl = 0.08838834764831845f; // 128^-0.5

    // ---- one fused conversion launch (both layers' weights + input) ----
    {
        ConvArgs a;
        const float* ins[NSEG]  = {x, W1, W2, Wq, Wk, Wv, Wo, Fw1, Fw2};
        hf*          outs[NSEG] = {x2, W12, W22, Wq2, Wk2, Wv2, Wo2, Fw12, Fw22};
        int n4[NSEG] = { MROWS*DL/4, DFF*DL/4, DL*DFF/4,
                         2*DL*DL/4, 2*DL*DL/4, 2*DL*DL/4, 2*DL*DL/4,
                         2*FH*DL/4, 2*DL*FH/4 };
        int acc0 = 0;
        for (int i = 0; i < NSEG; i++){ a.in[i]=ins[i]; a.out[i]=outs[i]; a.off[i]=acc0; acc0 += n4[i]; }
        a.off[NSEG] = acc0;
        convall_k<<<(acc0+255)/256,256>>>(a);
    }

    // ---- downsample ----
    gm(x2, W12, MROWS, DFF, DL, DL, DL,
       1,1,1.f, b1, nullptr, nullptr,0, H12, DFF);
    gm(H12, W22, MROWS, DL, DFF, DFF, DFF,
       0,0,1.f, b2, nullptr, X, DL, nullptr,0);

    for (int l = 0; l < 2; l++){
        const ll lw = (ll)l*DL*DL;

        layernorm_k<<<MROWS/4,128>>>(X, Hn2, ln1g+l*DL, ln1b+l*DL);
        // fused QKV: N=3072, region-selected B and bias, scl on Q region
        gm(Hn2, Wq2+lw, MROWS, 3*DL, DL, DL, DL,
           3,0,scl, bq+l*DL, nullptr, nullptr,0, nullptr, 0,
           Wk2+lw, Wv2+lw, bk+l*DL, bv+l*DL);

        flash_k<<<dim3(16,64),128,115712>>>(Q2, K2, Vh, O2);

        // X = X + O @ Wo^T + bo
        gm(O2, Wo2+lw, MROWS, DL, DL, DL, DL,
           0,0,1.f, bo+l*DL, X, X, DL, nullptr,0);

        layernorm_k<<<MROWS/4,128>>>(X, Hn2, ln2g+l*DL, ln2b+l*DL);
        gm(Hn2, Fw12+(ll)l*FH*DL, MROWS, FH, DL, DL, DL,
           1,1,1.f, Fb1+l*FH, nullptr, nullptr,0, F12, FH);
        float* dst = (l==1) ? out : X;
        gm(F12, Fw22+(ll)l*DL*FH, MROWS, DL, FH, FH, FH,
           0,0,1.f, Fb2+l*DL, X, dst, DL, nullptr,0);
    }
}